// round 1
// baseline (speedup 1.0000x reference)
#include <cuda_runtime.h>

#define T_STEPS 32
#define B_SZ    512
#define S_SZ    64
#define F_INDIM 128
#define H1      256
#define H2      256
#define H3      128

// Scratch (no cudaMalloc allowed): device globals.
__device__ float g_spk0[T_STEPS * B_SZ * F_INDIM];   // 8 MB
__device__ float g_spk1[T_STEPS * B_SZ * H1];        // 16 MB
__device__ float g_spk2[T_STEPS * B_SZ * H2];        // 16 MB
__device__ float g_Wt1[F_INDIM * H1];
__device__ float g_Wt2[H1 * H2];
__device__ float g_Wt3[H2 * H3];

// ---------------------------------------------------------------------------
// Transpose W[h,i] (H x IN, row-major) -> Wt[i,h] so layer kernels load
// weights coalesced across the h (thread) dimension.
// ---------------------------------------------------------------------------
__global__ void transpose_kernel(const float* __restrict__ W,
                                 float* __restrict__ Wt, int H, int IN) {
    int idx = blockIdx.x * blockDim.x + threadIdx.x;
    if (idx < H * IN) {
        int i = idx / H;
        int h = idx - i * H;
        Wt[idx] = W[h * IN + i];
    }
}

// ---------------------------------------------------------------------------
// Latency encoder. One thread per (b, f). Computes min/max over S (after
// gating), then t_idx per s, histogram over t, writes counts/64 to
// spikes0[t, b, f]. Matches snntorch spikegen.latency(normalize=True) math
// with fp32 ops in the same order as the jax reference.
// ---------------------------------------------------------------------------
__global__ void encode_kernel(const float* __restrict__ x,
                              float* __restrict__ out) {
    int gid = blockIdx.x * blockDim.x + threadIdx.x;   // b*128 + f
    int b = gid >> 7;
    int f = gid & 127;
    const float* xp = x + (size_t)b * (S_SZ * F_INDIM) + f;

    // pass 1: min/max of gated values over the sequence dim
    float mn = 1e30f, mx = -1e30f;
    for (int s = 0; s < S_SZ; ++s) {
        float v = xp[s * F_INDIM];
        float g = (v < 0.75f) ? 0.0f : v;
        mn = fminf(mn, g);
        mx = fmaxf(mx, g);
    }
    float denom = mx - mn + 1e-8f;

    // np.float32(np.log((0.01 + 1e-7) / 1e-7))
    const float TMAX = 11.512935464920229f;

    unsigned char cnt[T_STEPS];
#pragma unroll
    for (int t = 0; t < T_STEPS; ++t) cnt[t] = 0;

    // pass 2: latency code + histogram
    for (int s = 0; s < S_SZ; ++s) {
        float v = xp[s * F_INDIM];
        float g = (v < 0.75f) ? 0.0f : v;
        float xn = (g - mn) / denom;
        float d  = fmaxf(xn, 0.0100001f);          // clip(xn, LAT_THR+EPS)
        float lg = logf(d / (d - 0.01f));
        float tt = (lg * 31.0f) / TMAX;
        float tr = rintf(tt);                      // round half-to-even, like jnp.round
        tr = fminf(fmaxf(tr, 0.0f), 31.0f);
        cnt[(int)tr]++;
    }

    // mean over S == count * (1/64), exact in fp32
#pragma unroll
    for (int t = 0; t < T_STEPS; ++t) {
        out[((size_t)t * B_SZ + b) * F_INDIM + f] = (float)cnt[t] * (1.0f / 64.0f);
    }
}

// ---------------------------------------------------------------------------
// Fused Linear + LIF layer. One CTA per batch element b, one thread per
// output neuron h. Stage spk_in[t=0..31, b, :] in smem, register-block the
// 32 timestep accumulators, then run the LIF scan in registers and write
// the binary spikes.
// ---------------------------------------------------------------------------
template <int IN, int H>
__global__ void __launch_bounds__(H)
layer_kernel(const float* __restrict__ in, const float* __restrict__ Wt,
             const float* __restrict__ bias, float* __restrict__ out) {
    __shared__ float s_in[T_STEPS * IN];

    const int b = blockIdx.x;
    const int h = threadIdx.x;

    // Coalesced staging of all 32 timesteps of this batch element.
    for (int idx = h; idx < T_STEPS * IN; idx += H) {
        int t = idx / IN;
        int i = idx - t * IN;
        s_in[idx] = in[((size_t)t * B_SZ + b) * IN + i];
    }
    __syncthreads();

    float acc[T_STEPS];
#pragma unroll
    for (int t = 0; t < T_STEPS; ++t) acc[t] = 0.0f;

    // i-blocked by 4: 4 coalesced weight loads + 32 LDS.128 + 128 FFMA.
    for (int i = 0; i < IN; i += 4) {
        float w0 = Wt[(i + 0) * H + h];
        float w1 = Wt[(i + 1) * H + h];
        float w2 = Wt[(i + 2) * H + h];
        float w3 = Wt[(i + 3) * H + h];
#pragma unroll
        for (int t = 0; t < T_STEPS; ++t) {
            float4 s = *reinterpret_cast<const float4*>(&s_in[t * IN + i]);
            acc[t] = fmaf(w0, s.x, acc[t]);
            acc[t] = fmaf(w1, s.y, acc[t]);
            acc[t] = fmaf(w2, s.z, acc[t]);
            acc[t] = fmaf(w3, s.w, acc[t]);
        }
    }

    // LIF scan (reset-by-subtraction), fp32 ops in reference order
    // (no FMA contraction so rounding matches beta*mem + c - reset).
    const float bv = bias[h];
    float mem = 0.0f;
#pragma unroll
    for (int t = 0; t < T_STEPS; ++t) {
        float cur = __fadd_rn(acc[t], bv);
        float r   = (mem > 1.0f) ? 1.0f : 0.0f;
        mem = __fsub_rn(__fadd_rn(__fmul_rn(0.9f, mem), cur), r);
        out[((size_t)t * B_SZ + b) * H + h] = (mem > 1.0f) ? 1.0f : 0.0f;
    }
}

// ---------------------------------------------------------------------------
extern "C" void kernel_launch(void* const* d_in, const int* in_sizes, int n_in,
                              void* d_out, int out_size) {
    const float* x  = (const float*)d_in[0];
    const float* W1 = (const float*)d_in[1];
    const float* b1 = (const float*)d_in[2];
    const float* W2 = (const float*)d_in[3];
    const float* b2 = (const float*)d_in[4];
    const float* W3 = (const float*)d_in[5];
    const float* b3 = (const float*)d_in[6];
    float* out = (float*)d_out;

    float *spk0, *spk1, *spk2, *wt1, *wt2, *wt3;
    cudaGetSymbolAddress((void**)&spk0, g_spk0);
    cudaGetSymbolAddress((void**)&spk1, g_spk1);
    cudaGetSymbolAddress((void**)&spk2, g_spk2);
    cudaGetSymbolAddress((void**)&wt1, g_Wt1);
    cudaGetSymbolAddress((void**)&wt2, g_Wt2);
    cudaGetSymbolAddress((void**)&wt3, g_Wt3);

    // Weight transposes (tiny)
    transpose_kernel<<<(H1 * F_INDIM + 255) / 256, 256>>>(W1, wt1, H1, F_INDIM);
    transpose_kernel<<<(H2 * H1 + 255) / 256, 256>>>(W2, wt2, H2, H1);
    transpose_kernel<<<(H3 * H2 + 255) / 256, 256>>>(W3, wt3, H3, H2);

    // Encoder: one thread per (b, f)
    encode_kernel<<<(B_SZ * F_INDIM) / 256, 256>>>(x, spk0);

    // Fused Linear+LIF layers
    layer_kernel<F_INDIM, H1><<<B_SZ, H1>>>(spk0, wt1, b1, spk1);
    layer_kernel<H1, H2><<<B_SZ, H2>>>(spk1, wt2, b2, spk2);
    layer_kernel<H2, H3><<<B_SZ, H3>>>(spk2, wt3, b3, out);
}